// round 4
// baseline (speedup 1.0000x reference)
#include <cuda_runtime.h>
#include <cstdint>

#define DINLINE __device__ __forceinline__

namespace {
constexpr int kTlen = 1024;
constexpr int kF = 64;
constexpr int kH = 256;
constexpr int kK = 320;          // K = H + F (vec row = [h(256) | x(64)])
constexpr int kNJ = 16;          // CTAs per cluster (hidden stripes)
constexpr int kBT = 16;          // batch rows per CTA
constexpr int kNS = 16;          // k-slices (split-K)
constexpr int kKP = 10;          // f32x2 pairs per slice (20 k)
constexpr int kThreads = 256;
constexpr int kCtas = 128;       // 8 clusters x 16 CTAs
constexpr int kVecStride = kBT * kK;                    // one vec buffer
constexpr int kSmemFloats = 2 * kVecStride + kNS * kBT * 64 + 4 * kH + 4;
constexpr int kSmemBytes = kSmemFloats * 4;             // ~110.6 KB
}

DINLINE unsigned long long pack2(float lo, float hi) {
  unsigned long long r;
  asm("mov.b64 %0, {%1, %2};" : "=l"(r) : "f"(lo), "f"(hi));
  return r;
}
DINLINE void ffma2(unsigned long long& d, unsigned long long a, unsigned long long b) {
  asm("fma.rn.f32x2 %0, %1, %2, %0;" : "+l"(d) : "l"(a), "l"(b));
}
DINLINE float2 unpack2(unsigned long long v) {
  float lo, hi;
  asm("mov.b64 {%0, %1}, %2;" : "=f"(lo), "=f"(hi) : "l"(v));
  return make_float2(lo, hi);
}
DINLINE float sigmoidf_(float x) { return __fdividef(1.0f, 1.0f + __expf(-x)); }
DINLINE float tanhf_(float x) {
  const float e = __expf(2.0f * x);
  return 1.0f - __fdividef(2.0f, e + 1.0f);
}
DINLINE uint32_t smem_u32(const void* p) {
  uint32_t a;
  asm("{ .reg .u64 t; cvta.to.shared.u64 t, %1; cvt.u32.u64 %0, t; }"
      : "=r"(a) : "l"(p));
  return a;
}
DINLINE uint32_t cluster_rank() {
  uint32_t r;
  asm("mov.u32 %0, %%cluster_ctarank;" : "=r"(r));
  return r;
}
#define CLU_ARRIVE() asm volatile("barrier.cluster.arrive.aligned;" ::: "memory")
#define CLU_WAIT()   asm volatile("barrier.cluster.wait.aligned;" ::: "memory")

__global__ void __launch_bounds__(kThreads, 1)
lstm_seq2seq_kernel(const float* __restrict__ ts,
                    const float* __restrict__ Wih_e, const float* __restrict__ Whh_e,
                    const float* __restrict__ b_e,
                    const float* __restrict__ Wih_d, const float* __restrict__ Whh_d,
                    const float* __restrict__ b_d,
                    const float* __restrict__ Wout, const float* __restrict__ bout,
                    float* __restrict__ out) {
  extern __shared__ float smem[];
  float* vec = smem;                            // [2][16][320]
  float* partial = smem + 2 * kVecStride;       // [16 slices][16 b][64 c]
  float* wout_s = partial + kNS * kBT * 64;     // [4][256]
  float* bout_s = wout_s + 4 * kH;              // [4]

  const int tid = threadIdx.x;
  const int jstripe = (int)cluster_rank();      // 0..15 hidden stripe
  const int bstripe = blockIdx.x >> 4;          // 0..7  batch stripe

  const int slice = tid >> 4;   // 0..15 (GEMM k-slice)
  const int cg = tid & 15;      // 0..15 (gate-col group of 4)
  const int bl = tid >> 4;      // update: local batch row
  const int jj = tid & 15;      // update: local hidden col

  // prologue: zero h-slots of buffer 0; stage W_out tile + b_out
  for (int idx = tid; idx < kBT * kH; idx += kThreads)
    vec[(idx >> 8) * kK + (idx & 255)] = 0.0f;
  for (int idx = tid; idx < 4 * kH; idx += kThreads)
    wout_s[idx] = Wout[jstripe * 4 * kH + idx];
  if (tid < 4) bout_s[tid] = bout[jstripe * 4 + tid];

  unsigned long long w2[4][kKP];  // register-resident weights (f32x2 k-pairs)
  float bias[4];
  float cst = 0.0f;               // cell state in register across all 2048 steps

  auto load_w = [&](const float* Wih, const float* Whh, const float* bv) {
#pragma unroll
    for (int cc = 0; cc < 4; ++cc) {
      const int c = cg * 4 + cc;  // gate col 0..63 = gate*16 + j
      const int row = (c >> 4) * kH + jstripe * 16 + (c & 15);
#pragma unroll
      for (int kp = 0; kp < kKP; ++kp) {
        const int k0 = slice * 20 + 2 * kp;
        float a, b;
        if (k0 < kH) { a = Whh[row * kH + k0];        b = Whh[row * kH + k0 + 1]; }
        else         { a = Wih[row * kF + (k0 - kH)]; b = Wih[row * kF + (k0 - kH) + 1]; }
        w2[cc][kp] = pack2(a, b);
      }
    }
    const int jg = jstripe * 16 + jj;
#pragma unroll
    for (int g = 0; g < 4; ++g) bias[g] = bv[g * kH + jg];
  };

  const uint32_t vbase = smem_u32(vec);
  const int xrow = tid >> 4, xcol = tid & 15;   // x staging: one float4 / thread

  // stage x(0) into buffer 0 before the initial arrive
  {
    float4 vx = reinterpret_cast<const float4*>(
        ts + (((bstripe * kBT + xrow) * kTlen + 0) * kF))[xcol];
    reinterpret_cast<float4*>(vec + xrow * kK + kH)[xcol] = vx;
  }
  load_w(Wih_e, Whh_e, b_e);
  __syncthreads();
  CLU_ARRIVE();   // publish h0 + x0

  auto step = [&](int t, int tnext, int bt, bool dec) {
    float* vcur = vec + bt * kVecStride;
    float* vnext = vec + (bt ^ 1) * kVecStride;

    // issue next x load early: LDG latency overlaps the cluster wait
    float4 vx;
    if (tnext >= 0)
      vx = reinterpret_cast<const float4*>(
          ts + (((bstripe * kBT + xrow) * kTlen + tnext) * kF))[xcol];

    CLU_WAIT();   // h(t) now present in vcur (DSMEM-pushed by all peers)

    if (dec) {
      // out_t = h_pre @ Wout^T + bout (4-way split-K + shuffle reduce)
      const int o = tid >> 2, p = tid & 3;
      const int ob = o >> 2, ofi = o & 3;
      const float4* v4 = reinterpret_cast<const float4*>(vcur + ob * kK + p * 64);
      const float4* w4 = reinterpret_cast<const float4*>(wout_s + ofi * kH + p * 64);
      float s = 0.0f;
#pragma unroll
      for (int i = 0; i < 16; ++i) {
        const float4 a = v4[i], b = w4[i];
        s += a.x * b.x + a.y * b.y + a.z * b.z + a.w * b.w;
      }
      s += __shfl_xor_sync(0xffffffffu, s, 1);
      s += __shfl_xor_sync(0xffffffffu, s, 2);
      if (p == 0)
        out[((bstripe * kBT + ob) * kTlen + t) * kF + jstripe * 4 + ofi] =
            s + bout_s[ofi];
    }

    // gate GEMM partials: f32x2 FMAs, weights in registers
    const unsigned long long* vec2 =
        reinterpret_cast<const unsigned long long*>(vcur);
#pragma unroll
    for (int bg = 0; bg < 4; ++bg) {
      unsigned long long acc[4][4];
#pragma unroll
      for (int bb = 0; bb < 4; ++bb)
#pragma unroll
        for (int cc = 0; cc < 4; ++cc) acc[bb][cc] = 0ull;
#pragma unroll
      for (int kp = 0; kp < kKP; ++kp) {
#pragma unroll
        for (int bb = 0; bb < 4; ++bb) {
          const unsigned long long v =
              vec2[(bg * 4 + bb) * (kK / 2) + slice * kKP + kp];
#pragma unroll
          for (int cc = 0; cc < 4; ++cc) ffma2(acc[bb][cc], v, w2[cc][kp]);
        }
      }
#pragma unroll
      for (int bb = 0; bb < 4; ++bb) {
        const float2 f0 = unpack2(acc[bb][0]);
        const float2 f1 = unpack2(acc[bb][1]);
        const float2 f2 = unpack2(acc[bb][2]);
        const float2 f3 = unpack2(acc[bb][3]);
        *reinterpret_cast<float4*>(
            partial + (slice * kBT + bg * 4 + bb) * 64 + cg * 4) =
            make_float4(f0.x + f0.y, f1.x + f1.y, f2.x + f2.y, f3.x + f3.y);
      }
    }
    __syncthreads();

    // reduce 16 slices + LSTM cell update (c stays in register)
    {
      float gv[4];
#pragma unroll
      for (int g = 0; g < 4; ++g) {
        const float* pp = partial + bl * 64 + g * 16 + jj;
        float s = 0.0f;
#pragma unroll
        for (int sl = 0; sl < kNS; ++sl) s += pp[sl * kBT * 64];
        gv[g] = s + bias[g];
      }
      const float ig = sigmoidf_(gv[0]);
      const float fg = sigmoidf_(gv[1]);
      const float gg = tanhf_(gv[2]);
      const float og = sigmoidf_(gv[3]);
      cst = fg * cst + ig * gg;
      const float hv = og * tanhf_(cst);

      // push h(t+1) into ALL peers' vnext h-slot via DSMEM
      const uint32_t laddr =
          vbase + (uint32_t)(((bt ^ 1) * kBT + bl) * kK + jstripe * 16 + jj) * 4u;
#pragma unroll
      for (int r = 0; r < kNJ; ++r) {
        uint32_t raddr;
        asm volatile("mapa.shared::cluster.u32 %0, %1, %2;"
                     : "=r"(raddr) : "r"(laddr), "r"(r));
        asm volatile("st.shared::cluster.f32 [%0], %1;" :: "r"(raddr), "f"(hv));
      }
    }

    // stage x(tnext) into vnext (local smem; ordered by arrive/wait release-acquire)
    if (tnext >= 0)
      reinterpret_cast<float4*>(vnext + xrow * kK + kH)[xcol] = vx;

    CLU_ARRIVE();  // release: h push + x stage published to cluster
  };

  // encoder: t ascending; step s stages x for step s+1 (last stages dec's first x)
  for (int s = 0; s < kTlen; ++s)
    step(s, (s + 1 < kTlen) ? s + 1 : kTlen - 1, s & 1, false);

  // decoder weight reload overlaps the in-flight cluster barrier
  load_w(Wih_d, Whh_d, b_d);

  // decoder: t descending, emit projection of pre-update h
  for (int i = 0; i < kTlen; ++i)
    step(kTlen - 1 - i, (i + 1 < kTlen) ? kTlen - 2 - i : -1, i & 1, true);

  CLU_WAIT();  // match final arrive before exit
}

extern "C" void kernel_launch(void* const* d_in, const int* in_sizes, int n_in,
                              void* d_out, int out_size) {
  cudaFuncSetAttribute(lstm_seq2seq_kernel,
                       cudaFuncAttributeMaxDynamicSharedMemorySize, kSmemBytes);
  cudaFuncSetAttribute(lstm_seq2seq_kernel,
                       cudaFuncAttributeNonPortableClusterSizeAllowed, 1);

  void* args[] = {(void*)&d_in[0], (void*)&d_in[1], (void*)&d_in[2],
                  (void*)&d_in[3], (void*)&d_in[4], (void*)&d_in[5],
                  (void*)&d_in[6], (void*)&d_in[7], (void*)&d_in[8],
                  (void*)&d_out};
  const float* ts = (const float*)d_in[0];
  const float* a1 = (const float*)d_in[1];
  const float* a2 = (const float*)d_in[2];
  const float* a3 = (const float*)d_in[3];
  const float* a4 = (const float*)d_in[4];
  const float* a5 = (const float*)d_in[5];
  const float* a6 = (const float*)d_in[6];
  const float* a7 = (const float*)d_in[7];
  const float* a8 = (const float*)d_in[8];
  float* o = (float*)d_out;
  (void)args;

  cudaLaunchConfig_t cfg = {};
  cfg.gridDim = dim3(kCtas, 1, 1);
  cfg.blockDim = dim3(kThreads, 1, 1);
  cfg.dynamicSmemBytes = kSmemBytes;
  cfg.stream = 0;
  cudaLaunchAttribute attrs[1];
  attrs[0].id = cudaLaunchAttributeClusterDimension;
  attrs[0].val.clusterDim = {kNJ, 1, 1};
  cfg.attrs = attrs;
  cfg.numAttrs = 1;
  cudaLaunchKernelEx(&cfg, lstm_seq2seq_kernel,
                     ts, a1, a2, a3, a4, a5, a6, a7, a8, o);
}

// round 5
// speedup vs baseline: 1.9239x; 1.9239x over previous
#include <cuda_runtime.h>
#include <cstdint>

#define DINLINE __device__ __forceinline__

namespace {
constexpr int kTlen = 1024;
constexpr int kF = 64;
constexpr int kH = 256;
constexpr int kK = 320;          // K = H + F (vec = [h | x])
constexpr int kNJ = 16;          // CTAs per barrier group (hidden stripes)
constexpr int kBT = 16;          // batch rows per CTA
constexpr int kNS = 16;          // k-slices (split-K)
constexpr int kKP = 10;          // f32x2 pairs per slice
constexpr int kThreads = 256;
constexpr int kCtas = 128;       // 8 batch stripes x 16 hidden stripes
constexpr int kSmemBytes = 120 * 1024;  // force 1 CTA/SM => all CTAs resident
}

__device__ float g_h[2][128 * 256];
__device__ unsigned g_cnt[8 * 64];  // one counter per group, 256B apart

__global__ void init_barriers_kernel() {
  if (threadIdx.x < 8) g_cnt[threadIdx.x * 64] = 0u;
}

DINLINE unsigned long long pack2(float lo, float hi) {
  unsigned long long r;
  asm("mov.b64 %0, {%1, %2};" : "=l"(r) : "f"(lo), "f"(hi));
  return r;
}
DINLINE void ffma2(unsigned long long& d, unsigned long long a, unsigned long long b) {
  asm("fma.rn.f32x2 %0, %1, %2, %0;" : "+l"(d) : "l"(a), "l"(b));
}
DINLINE float2 unpack2(unsigned long long v) {
  float lo, hi;
  asm("mov.b64 {%0, %1}, %2;" : "=f"(lo), "=f"(hi) : "l"(v));
  return make_float2(lo, hi);
}
DINLINE float sigmoidf_(float x) { return __fdividef(1.0f, 1.0f + __expf(-x)); }
DINLINE float tanhf_(float x) {
  const float e = __expf(2.0f * x);
  return 1.0f - __fdividef(2.0f, e + 1.0f);
}

__global__ void __launch_bounds__(kThreads, 1)
lstm_seq2seq_kernel(const float* __restrict__ ts,
                    const float* __restrict__ Wih_e, const float* __restrict__ Whh_e,
                    const float* __restrict__ b_e,
                    const float* __restrict__ Wih_d, const float* __restrict__ Whh_d,
                    const float* __restrict__ b_d,
                    const float* __restrict__ Wout, const float* __restrict__ bout,
                    float* __restrict__ out) {
  extern __shared__ float smem[];
  float* vec = smem;                         // [16][320]  vec = [h_t | x_t]
  float* partial = smem + kBT * kK;          // [16 slices][16 b][64 c]
  float* wout_s = partial + kNS * kBT * 64;  // [4][256]
  float* bout_s = wout_s + 4 * kH;           // [4]

  const int tid = threadIdx.x;
  const int jstripe = blockIdx.x & (kNJ - 1);
  const int bstripe = blockIdx.x >> 4;

  const int slice = tid >> 4;   // 0..15  (GEMM k-slice)
  const int cg = tid & 15;      // 0..15  (gate-col group of 4)
  const int bl = tid >> 4;      // update: local batch row
  const int jj = tid & 15;      // update: local hidden col

  unsigned* cnt = &g_cnt[bstripe * 64];
  unsigned barno = 0;

  // h0 = 0 for owned (b,j); stage W_out tile + b_out
  g_h[0][(bstripe * kBT + bl) * kH + jstripe * 16 + jj] = 0.0f;
  for (int idx = tid; idx < 4 * kH; idx += kThreads)
    wout_s[idx] = Wout[jstripe * 4 * kH + idx];
  if (tid < 4) bout_s[tid] = bout[jstripe * 4 + tid];

  unsigned long long w2[4][kKP];  // register-resident weights (f32x2 k-pairs)
  float bias[4];
  float cst = 0.0f;               // cell state, register-resident across ALL steps

  auto load_w = [&](const float* Wih, const float* Whh, const float* bv) {
#pragma unroll
    for (int cc = 0; cc < 4; ++cc) {
      const int c = cg * 4 + cc;  // gate col 0..63 = gate*16 + j
      const int row = (c >> 4) * kH + jstripe * 16 + (c & 15);
#pragma unroll
      for (int kp = 0; kp < kKP; ++kp) {
        const int k0 = slice * 20 + 2 * kp;
        float a, b;
        if (k0 < kH) { a = Whh[row * kH + k0];        b = Whh[row * kH + k0 + 1]; }
        else         { a = Wih[row * kF + (k0 - kH)]; b = Wih[row * kF + (k0 - kH) + 1]; }
        w2[cc][kp] = pack2(a, b);
      }
    }
    const int jg = jstripe * 16 + jj;
#pragma unroll
    for (int g = 0; g < 4; ++g) bias[g] = bv[g * kH + jg];
  };

  // monotonic single-atomic barrier (counter zeroed by init kernel per launch)
  auto arrive = [&]() {
    __syncthreads();           // all h stores of this CTA issued
    if (tid == 0) {
      ++barno;
      __threadfence();
      atomicAdd(cnt, 1u);
    }
  };
  auto wait = [&]() {
    if (tid == 0) {
      const unsigned target = (unsigned)kNJ * barno;
      unsigned v;
      do {
        asm volatile("ld.acquire.gpu.u32 %0, [%1];" : "=r"(v) : "l"(cnt));
      } while ((int)(v - target) < 0);
    }
    __syncthreads();
  };

  auto step = [&](int t, int buf, bool dec) {
    // prefetch x(t): LDG latency hides under the barrier spin
    const int xrow = tid >> 4, xcol = tid & 15;
    const float4 vx = reinterpret_cast<const float4*>(
        ts + (((bstripe * kBT + xrow) * kTlen + t) * kF))[xcol];

    wait();  // h(t) visible in g_h[buf]

    // stage vec = [h_t | x_t] into smem (coalesced)
    {
      const int r0 = tid >> 6, kc = tid & 63;
#pragma unroll
      for (int p = 0; p < 4; ++p) {
        const int row = p * 4 + r0;
        float4 v = reinterpret_cast<const float4*>(
            g_h[buf] + (bstripe * kBT + row) * kH)[kc];
        reinterpret_cast<float4*>(vec + row * kK)[kc] = v;
      }
      reinterpret_cast<float4*>(vec + xrow * kK + kH)[xcol] = vx;
    }
    __syncthreads();

    // gate GEMM partials: f32x2 FMAs, weights in registers
    const unsigned long long* vec2 = reinterpret_cast<const unsigned long long*>(vec);
#pragma unroll
    for (int bg = 0; bg < 4; ++bg) {
      unsigned long long acc[4][4];
#pragma unroll
      for (int bb = 0; bb < 4; ++bb)
#pragma unroll
        for (int cc = 0; cc < 4; ++cc) acc[bb][cc] = 0ull;
#pragma unroll
      for (int kp = 0; kp < kKP; ++kp) {
#pragma unroll
        for (int bb = 0; bb < 4; ++bb) {
          const unsigned long long v =
              vec2[(bg * 4 + bb) * (kK / 2) + slice * kKP + kp];
#pragma unroll
          for (int cc = 0; cc < 4; ++cc) ffma2(acc[bb][cc], v, w2[cc][kp]);
        }
      }
#pragma unroll
      for (int bb = 0; bb < 4; ++bb) {
        const float2 f0 = unpack2(acc[bb][0]);
        const float2 f1 = unpack2(acc[bb][1]);
        const float2 f2 = unpack2(acc[bb][2]);
        const float2 f3 = unpack2(acc[bb][3]);
        *reinterpret_cast<float4*>(
            partial + (slice * kBT + bg * 4 + bb) * 64 + cg * 4) =
            make_float4(f0.x + f0.y, f1.x + f1.y, f2.x + f2.y, f3.x + f3.y);
      }
    }
    __syncthreads();

    // reduce 16 slices + LSTM cell update (c stays in register)
    {
      float gv[4];
#pragma unroll
      for (int g = 0; g < 4; ++g) {
        const float* pp = partial + bl * 64 + g * 16 + jj;
        float s = 0.0f;
#pragma unroll
        for (int sl = 0; sl < kNS; ++sl) s += pp[sl * kBT * 64];
        gv[g] = s + bias[g];
      }
      const float ig = sigmoidf_(gv[0]);
      const float fg = sigmoidf_(gv[1]);
      const float gg = tanhf_(gv[2]);
      const float og = sigmoidf_(gv[3]);
      cst = fg * cst + ig * gg;
      const float hv = og * tanhf_(cst);
      g_h[buf ^ 1][(bstripe * kBT + bl) * kH + jstripe * 16 + jj] = hv;
    }
    arrive();  // publish h(t+1); peers proceed while we do the projection

    if (dec) {
      // out_t = h_pre @ Wout^T + bout — OFF the serial path (vec still holds h_t)
      const int o = tid >> 2, p = tid & 3;
      const int ob = o >> 2, ofi = o & 3;
      const float4* v4 = reinterpret_cast<const float4*>(vec + ob * kK + p * 64);
      const float4* w4 = reinterpret_cast<const float4*>(wout_s + ofi * kH + p * 64);
      float s = 0.0f;
#pragma unroll
      for (int i = 0; i < 16; ++i) {
        const float4 a = v4[i], b = w4[i];
        s += a.x * b.x + a.y * b.y + a.z * b.z + a.w * b.w;
      }
      s += __shfl_xor_sync(0xffffffffu, s, 1);
      s += __shfl_xor_sync(0xffffffffu, s, 2);
      if (p == 0)
        out[((bstripe * kBT + ob) * kTlen + t) * kF + jstripe * 4 + ofi] =
            s + bout_s[ofi];
    }
  };

  load_w(Wih_e, Whh_e, b_e);
  arrive();  // publish h0

  for (int t = 0; t < kTlen; ++t) step(t, t & 1, false);

  load_w(Wih_d, Whh_d, b_d);
  for (int i = 0; i < kTlen; ++i) step(kTlen - 1 - i, i & 1, true);
}

extern "C" void kernel_launch(void* const* d_in, const int* in_sizes, int n_in,
                              void* d_out, int out_size) {
  cudaFuncSetAttribute(lstm_seq2seq_kernel,
                       cudaFuncAttributeMaxDynamicSharedMemorySize, kSmemBytes);
  init_barriers_kernel<<<1, 32>>>();
  lstm_seq2seq_kernel<<<kCtas, kThreads, kSmemBytes>>>(
      (const float*)d_in[0], (const float*)d_in[1], (const float*)d_in[2],
      (const float*)d_in[3], (const float*)d_in[4], (const float*)d_in[5],
      (const float*)d_in[6], (const float*)d_in[7], (const float*)d_in[8],
      (float*)d_out);
}